// round 10
// baseline (speedup 1.0000x reference)
#include <cuda_runtime.h>
#include <cuda_fp16.h>
#include <cstdint>

namespace {

constexpr int Bb = 2, Hh = 16, Tt = 4096, Dd = 64;
constexpr int BM = 64;             // q rows per CTA (4 warps x 16 rows)
constexpr int BN = 64;             // kv rows per tile
constexpr int STAGES = 4;
constexpr int KSTR = 72;           // smem row stride (halves): conflict-free ldmatrix
constexpr int STAGE_HALVES = 2 * BN * KSTR;                  // K tile + V tile
constexpr int SMEM_BYTES = STAGES * STAGE_HALVES * 2;        // 73728 B; x3 CTAs = 221KB
constexpr float QSCALE = 0.125f * 1.44269504088896340736f;   // 1/sqrt(64) * log2(e)

// fp16 copies of K and V (written by conv_kv, read by fa_fwd)
__device__ __half g_kh[Bb * Hh * Tt * Dd];
__device__ __half g_vh[Bb * Hh * Tt * Dd];

__device__ __forceinline__ uint32_t cvta_s(const void* p) {
    return (uint32_t)__cvta_generic_to_shared(p);
}

__device__ __forceinline__ float ex2f(float x) {
    float y;
    asm("ex2.approx.f32 %0, %1;" : "=f"(y) : "f"(x));
    return y;
}

__device__ __forceinline__ void cpa16(uint32_t dst, const void* src) {
    asm volatile("cp.async.cg.shared.global [%0], [%1], 16;"
                 :: "r"(dst), "l"(src) : "memory");
}

__device__ __forceinline__ void cpa_commit() {
    asm volatile("cp.async.commit_group;" ::: "memory");
}

template <int N>
__device__ __forceinline__ void cpa_wait() {
    asm volatile("cp.async.wait_group %0;" :: "n"(N) : "memory");
}

__device__ __forceinline__ void ldsm4(uint32_t& r0, uint32_t& r1, uint32_t& r2,
                                      uint32_t& r3, uint32_t addr) {
    asm volatile("ldmatrix.sync.aligned.m8n8.x4.shared.b16 {%0,%1,%2,%3}, [%4];"
                 : "=r"(r0), "=r"(r1), "=r"(r2), "=r"(r3) : "r"(addr));
}

__device__ __forceinline__ void ldsm4t(uint32_t& r0, uint32_t& r1, uint32_t& r2,
                                       uint32_t& r3, uint32_t addr) {
    asm volatile("ldmatrix.sync.aligned.m8n8.x4.trans.shared.b16 {%0,%1,%2,%3}, [%4];"
                 : "=r"(r0), "=r"(r1), "=r"(r2), "=r"(r3) : "r"(addr));
}

__device__ __forceinline__ void mma16816(float d[4], const uint32_t a[4],
                                         uint32_t b0, uint32_t b1) {
    asm volatile(
        "mma.sync.aligned.m16n8k16.row.col.f32.f16.f16.f32 "
        "{%0,%1,%2,%3}, {%4,%5,%6,%7}, {%8,%9}, {%0,%1,%2,%3};"
        : "+f"(d[0]), "+f"(d[1]), "+f"(d[2]), "+f"(d[3])
        : "r"(a[0]), "r"(a[1]), "r"(a[2]), "r"(a[3]), "r"(b0), "r"(b1));
}

__device__ __forceinline__ uint32_t packh2(float a, float b) {
    uint32_t r;
    asm("cvt.rn.f16x2.f32 %0, %2, %1;" : "=r"(r) : "f"(a), "f"(b));
    return r;   // lower half = a, upper = b
}

// ---- pre-pass: K,V f32 -> fp16 scratch (same rounding as mma inputs had) ----
__global__ void __launch_bounds__(256)
conv_kv(const float* __restrict__ K, const float* __restrict__ V) {
    const int N4 = Bb * Hh * Tt * Dd / 4;
    __half2* kh2 = reinterpret_cast<__half2*>(g_kh);
    __half2* vh2 = reinterpret_cast<__half2*>(g_vh);
    for (int i = blockIdx.x * blockDim.x + threadIdx.x; i < N4;
         i += gridDim.x * blockDim.x) {
        float4 a = reinterpret_cast<const float4*>(K)[i];
        float4 b = reinterpret_cast<const float4*>(V)[i];
        kh2[2 * i]     = __floats2half2_rn(a.x, a.y);
        kh2[2 * i + 1] = __floats2half2_rn(a.z, a.w);
        vh2[2 * i]     = __floats2half2_rn(b.x, b.y);
        vh2[2 * i + 1] = __floats2half2_rn(b.z, b.w);
    }
}

__global__ void __launch_bounds__(128, 3)
fa_fwd(const float* __restrict__ Q, float* __restrict__ O) {
    extern __shared__ __half sm_[];

    const int tid  = threadIdx.x;
    const int warp = tid >> 5;
    const int lane = tid & 31;
    const int g = lane >> 2;
    const int t = lane & 3;

    const int bh    = blockIdx.y;
    const int qb    = (int)gridDim.x - 1 - (int)blockIdx.x;  // longest-first
    const int qbase = qb * BM;
    const size_t base = (size_t)bh * Tt * Dd;
    const float*  Qp = Q + base;
    const __half* Kh = g_kh + base;
    const __half* Vh = g_vh + base;
    float*        Op = O + base;

    const int wrow = warp * 16;            // warp covers rows [wrow, wrow+16)
    const int jmax = qb;                   // kv tiles with kvbase <= qbase+63

    // cp.async producer indexing: 2 threads per row, 4x16B chunks each
    const int prow = tid >> 1;
    const int pcol = (tid & 1) * 32;       // halves
    const uint32_t smem_u32 = cvta_s(sm_);

    auto issue_tile = [&](int j) {
        if (j <= jmax) {
            const int st = (j & (STAGES - 1)) * STAGE_HALVES;
            const __half* ksrc = Kh + (size_t)(j * BN + prow) * Dd + pcol;
            const __half* vsrc = Vh + (size_t)(j * BN + prow) * Dd + pcol;
            uint32_t kdst = smem_u32 + (st + prow * KSTR + pcol) * 2;
            uint32_t vdst = kdst + BN * KSTR * 2;
#pragma unroll
            for (int i = 0; i < 4; i++) cpa16(kdst + i * 16, ksrc + i * 8);
#pragma unroll
            for (int i = 0; i < 4; i++) cpa16(vdst + i * 16, vsrc + i * 8);
        }
        cpa_commit();
    };

    // ---- Q A-fragments straight from gmem (pre-scaled into exp2 domain) ----
    uint32_t qa[4][4];
    {
        const float* q0 = Qp + (size_t)(qbase + wrow + g) * Dd;
        const float* q1 = q0 + 8 * Dd;
#pragma unroll
        for (int ks = 0; ks < 4; ks++) {
            int col = ks * 16 + t * 2;
            float2 x0 = *reinterpret_cast<const float2*>(q0 + col);
            float2 x1 = *reinterpret_cast<const float2*>(q1 + col);
            float2 x2 = *reinterpret_cast<const float2*>(q0 + col + 8);
            float2 x3 = *reinterpret_cast<const float2*>(q1 + col + 8);
            qa[ks][0] = packh2(x0.x * QSCALE, x0.y * QSCALE);
            qa[ks][1] = packh2(x1.x * QSCALE, x1.y * QSCALE);
            qa[ks][2] = packh2(x2.x * QSCALE, x2.y * QSCALE);
            qa[ks][3] = packh2(x3.x * QSCALE, x3.y * QSCALE);
        }
    }

    // ---- pipeline prologue: tiles 0..STAGES-2 in flight ----
#pragma unroll
    for (int j = 0; j < STAGES - 1; j++) issue_tile(j);

    float o[8][4];
#pragma unroll
    for (int nd = 0; nd < 8; nd++) {
        o[nd][0] = 0.f; o[nd][1] = 0.f; o[nd][2] = 0.f; o[nd][3] = 0.f;
    }
    const float NEGINF = __int_as_float(0xff800000u);
    float m_lo = NEGINF, m_hi = NEGINF, l_lo = 0.f, l_hi = 0.f;

    for (int j = 0; j <= jmax; j++) {
        cpa_wait<STAGES - 2>();     // tile j landed (this thread's groups)
        __syncthreads();            // visible to all; stage (j-1) fully consumed
        issue_tile(j + STAGES - 1); // refill oldest stage

        const int st = (j & (STAGES - 1)) * STAGE_HALVES;
        const __half* kt = sm_ + st;
        const __half* vt = kt + BN * KSTR;
        const int kvbase = j * BN;

        const bool active = (kvbase <= qbase + wrow + 15);
        if (active) {
            // ---- S = Q K^T ----
            float s[8][4];
#pragma unroll
            for (int n = 0; n < 8; n++) {
                s[n][0] = 0.f; s[n][1] = 0.f; s[n][2] = 0.f; s[n][3] = 0.f;
            }
            const int rowa = (lane & 7);
            const int cola = 8 * (lane >> 3);
#pragma unroll
            for (int n = 0; n < 8; n++) {
                uint32_t b[8];
                uint32_t addr = cvta_s(kt + (8 * n + rowa) * KSTR + cola);
                ldsm4(b[0], b[1], b[2], b[3], addr);
                ldsm4(b[4], b[5], b[6], b[7], addr + 64);   // +32 halves
#pragma unroll
                for (int ks = 0; ks < 4; ks++)
                    mma16816(s[n], qa[ks], b[2 * ks], b[2 * ks + 1]);
            }

            // ---- causal mask (straddling tiles only) ----
            if (kvbase + BN - 1 > qbase + wrow) {
                const int q_lo = qbase + wrow + g;
                const int q_hi = q_lo + 8;
#pragma unroll
                for (int n = 0; n < 8; n++) {
                    int c = kvbase + n * 8 + t * 2;
                    if (c     > q_lo) s[n][0] = NEGINF;
                    if (c + 1 > q_lo) s[n][1] = NEGINF;
                    if (c     > q_hi) s[n][2] = NEGINF;
                    if (c + 1 > q_hi) s[n][3] = NEGINF;
                }
            }

            // ---- online softmax (exp2 domain) ----
            float tl = NEGINF, th = NEGINF;
#pragma unroll
            for (int n = 0; n < 8; n++) {
                tl = fmaxf(tl, fmaxf(s[n][0], s[n][1]));
                th = fmaxf(th, fmaxf(s[n][2], s[n][3]));
            }
            tl = fmaxf(tl, __shfl_xor_sync(0xffffffffu, tl, 1));
            tl = fmaxf(tl, __shfl_xor_sync(0xffffffffu, tl, 2));
            th = fmaxf(th, __shfl_xor_sync(0xffffffffu, th, 1));
            th = fmaxf(th, __shfl_xor_sync(0xffffffffu, th, 2));

            float mn_lo = fmaxf(m_lo, tl);
            float mn_hi = fmaxf(m_hi, th);
            float al = ex2f(m_lo - mn_lo);
            float ah = ex2f(m_hi - mn_hi);
            m_lo = mn_lo; m_hi = mn_hi;

            float sl = 0.f, sh = 0.f;
            uint32_t ph[8][2];
#pragma unroll
            for (int n = 0; n < 8; n++) {
                float e0 = ex2f(s[n][0] - m_lo);
                float e1 = ex2f(s[n][1] - m_lo);
                float e2 = ex2f(s[n][2] - m_hi);
                float e3 = ex2f(s[n][3] - m_hi);
                sl += e0 + e1;
                sh += e2 + e3;
                ph[n][0] = packh2(e0, e1);
                ph[n][1] = packh2(e2, e3);
            }
            l_lo = l_lo * al + sl;
            l_hi = l_hi * ah + sh;
#pragma unroll
            for (int nd = 0; nd < 8; nd++) {
                o[nd][0] *= al; o[nd][1] *= al;
                o[nd][2] *= ah; o[nd][3] *= ah;
            }

            // ---- O += P V ----
            const int rowv0 = 8 * ((lane >> 3) & 1) + (lane & 7);
            const int cv = (lane >> 4);
#pragma unroll
            for (int ks = 0; ks < 4; ks++) {
                const uint32_t a[4] = {ph[2 * ks][0], ph[2 * ks][1],
                                       ph[2 * ks + 1][0], ph[2 * ks + 1][1]};
                const __half* vrow = vt + (16 * ks + rowv0) * KSTR;
#pragma unroll
                for (int p = 0; p < 4; p++) {
                    uint32_t r0, r1, r2, r3;
                    ldsm4t(r0, r1, r2, r3, cvta_s(vrow + 8 * (2 * p + cv)));
                    mma16816(o[2 * p],     a, r0, r1);
                    mma16816(o[2 * p + 1], a, r2, r3);
                }
            }
        }
    }

    // ---- finalize ----
    l_lo += __shfl_xor_sync(0xffffffffu, l_lo, 1);
    l_lo += __shfl_xor_sync(0xffffffffu, l_lo, 2);
    l_hi += __shfl_xor_sync(0xffffffffu, l_hi, 1);
    l_hi += __shfl_xor_sync(0xffffffffu, l_hi, 2);
    const float il = 1.f / l_lo;
    const float ih = 1.f / l_hi;

    const int r_lo = qbase + wrow + g;
#pragma unroll
    for (int nd = 0; nd < 8; nd++) {
        int col = nd * 8 + t * 2;
        *reinterpret_cast<float2*>(Op + (size_t)r_lo * Dd + col) =
            make_float2(o[nd][0] * il, o[nd][1] * il);
        *reinterpret_cast<float2*>(Op + (size_t)(r_lo + 8) * Dd + col) =
            make_float2(o[nd][2] * ih, o[nd][3] * ih);
    }
}

}  // namespace

extern "C" void kernel_launch(void* const* d_in, const int* in_sizes, int n_in,
                              void* d_out, int out_size) {
    (void)in_sizes; (void)n_in; (void)out_size;
    const float* q = (const float*)d_in[0];
    const float* k = (const float*)d_in[1];
    const float* v = (const float*)d_in[2];
    float*       o = (float*)d_out;

    conv_kv<<<2048, 256>>>(k, v);

    cudaFuncSetAttribute(fa_fwd, cudaFuncAttributeMaxDynamicSharedMemorySize,
                         SMEM_BYTES);
    dim3 grid(Tt / BM, Bb * Hh);
    fa_fwd<<<grid, 128, SMEM_BYTES>>>(q, o);
}

// round 12
// speedup vs baseline: 1.2948x; 1.2948x over previous
#include <cuda_runtime.h>
#include <cuda_fp16.h>
#include <cstdint>

namespace {

constexpr int Bb = 2, Hh = 16, Tt = 4096, Dd = 64;
constexpr int BM = 128;            // q rows per CTA (4 warps x 32 rows)
constexpr int BN = 64;             // kv rows per tile
constexpr int STAGES = 4;
constexpr int KSTR = 72;           // smem row stride (halves): conflict-free ldmatrix
constexpr int STAGE_HALVES = 2 * BN * KSTR;                  // K tile + V tile
constexpr int SMEM_BYTES = STAGES * STAGE_HALVES * 2;        // 73728
constexpr float QSCALE = 0.125f * 1.44269504088896340736f;   // 1/sqrt(64) * log2(e)
constexpr uint32_t ONESH2 = 0x3C003C00u;                     // half2(1.0, 1.0)

// fp16 copies of K and V (written by conv_kv, read by fa_fwd)
__device__ __half g_kh[Bb * Hh * Tt * Dd];
__device__ __half g_vh[Bb * Hh * Tt * Dd];

__device__ __forceinline__ uint32_t cvta_s(const void* p) {
    return (uint32_t)__cvta_generic_to_shared(p);
}

__device__ __forceinline__ float ex2f(float x) {
    float y;
    asm("ex2.approx.f32 %0, %1;" : "=f"(y) : "f"(x));
    return y;
}

__device__ __forceinline__ uint32_t ex2h2(uint32_t x) {
    uint32_t y;
    asm("ex2.approx.f16x2 %0, %1;" : "=r"(y) : "r"(x));
    return y;
}

__device__ __forceinline__ void cpa16(uint32_t dst, const void* src) {
    asm volatile("cp.async.cg.shared.global [%0], [%1], 16;"
                 :: "r"(dst), "l"(src) : "memory");
}

__device__ __forceinline__ void cpa_commit() {
    asm volatile("cp.async.commit_group;" ::: "memory");
}

template <int N>
__device__ __forceinline__ void cpa_wait() {
    asm volatile("cp.async.wait_group %0;" :: "n"(N) : "memory");
}

__device__ __forceinline__ void ldsm4(uint32_t& r0, uint32_t& r1, uint32_t& r2,
                                      uint32_t& r3, uint32_t addr) {
    asm volatile("ldmatrix.sync.aligned.m8n8.x4.shared.b16 {%0,%1,%2,%3}, [%4];"
                 : "=r"(r0), "=r"(r1), "=r"(r2), "=r"(r3) : "r"(addr));
}

__device__ __forceinline__ void ldsm4t(uint32_t& r0, uint32_t& r1, uint32_t& r2,
                                       uint32_t& r3, uint32_t addr) {
    asm volatile("ldmatrix.sync.aligned.m8n8.x4.trans.shared.b16 {%0,%1,%2,%3}, [%4];"
                 : "=r"(r0), "=r"(r1), "=r"(r2), "=r"(r3) : "r"(addr));
}

__device__ __forceinline__ void mma16816(float d[4], const uint32_t a[4],
                                         uint32_t b0, uint32_t b1) {
    asm volatile(
        "mma.sync.aligned.m16n8k16.row.col.f32.f16.f16.f32 "
        "{%0,%1,%2,%3}, {%4,%5,%6,%7}, {%8,%9}, {%0,%1,%2,%3};"
        : "+f"(d[0]), "+f"(d[1]), "+f"(d[2]), "+f"(d[3])
        : "r"(a[0]), "r"(a[1]), "r"(a[2]), "r"(a[3]), "r"(b0), "r"(b1));
}

__device__ __forceinline__ uint32_t packh2(float a, float b) {
    uint32_t r;
    asm("cvt.rn.f16x2.f32 %0, %2, %1;" : "=r"(r) : "f"(a), "f"(b));
    return r;   // lower half = a, upper = b
}

// ---- pre-pass: K,V f32 -> fp16 scratch (same rounding as before) ----
__global__ void __launch_bounds__(256)
conv_kv(const float* __restrict__ K, const float* __restrict__ V) {
    const int N4 = Bb * Hh * Tt * Dd / 4;
    __half2* kh2 = reinterpret_cast<__half2*>(g_kh);
    __half2* vh2 = reinterpret_cast<__half2*>(g_vh);
    for (int i = blockIdx.x * blockDim.x + threadIdx.x; i < N4;
         i += gridDim.x * blockDim.x) {
        float4 a = reinterpret_cast<const float4*>(K)[i];
        float4 b = reinterpret_cast<const float4*>(V)[i];
        kh2[2 * i]     = __floats2half2_rn(a.x, a.y);
        kh2[2 * i + 1] = __floats2half2_rn(a.z, a.w);
        vh2[2 * i]     = __floats2half2_rn(b.x, b.y);
        vh2[2 * i + 1] = __floats2half2_rn(b.z, b.w);
    }
}

// online-softmax update for one 16-row subtile.
// fp16x2 exp2 (argument formed in f32), row-sum via ones-MMA (full row sum,
// duplicated across the quad -> no lane reduction needed, ever).
__device__ __forceinline__ void softmax_sub(float s[8][4], float& m_lo, float& m_hi,
                                            float& l_lo, float& l_hi,
                                            float o[8][4], uint32_t ph[8][2]) {
    const float NEGINF = __int_as_float(0xff800000u);
    float tl = NEGINF, th = NEGINF;
#pragma unroll
    for (int n = 0; n < 8; n++) {
        tl = fmaxf(tl, fmaxf(s[n][0], s[n][1]));
        th = fmaxf(th, fmaxf(s[n][2], s[n][3]));
    }
    tl = fmaxf(tl, __shfl_xor_sync(0xffffffffu, tl, 1));
    tl = fmaxf(tl, __shfl_xor_sync(0xffffffffu, tl, 2));
    th = fmaxf(th, __shfl_xor_sync(0xffffffffu, th, 1));
    th = fmaxf(th, __shfl_xor_sync(0xffffffffu, th, 2));

    float mn_lo = fmaxf(m_lo, tl);
    float mn_hi = fmaxf(m_hi, th);
    float al = ex2f(m_lo - mn_lo);
    float ah = ex2f(m_hi - mn_hi);
    m_lo = mn_lo; m_hi = mn_hi;

    // p = exp2(s - m), two elements per MUFU op
#pragma unroll
    for (int n = 0; n < 8; n++) {
        float d0 = s[n][0] - m_lo;
        float d1 = s[n][1] - m_lo;
        float d2 = s[n][2] - m_hi;
        float d3 = s[n][3] - m_hi;
        ph[n][0] = ex2h2(packh2(d0, d1));
        ph[n][1] = ex2h2(packh2(d2, d3));
    }

    // row sums via MMA with B = ones: lt[0] = full row sum (lo), lt[2] = (hi)
    float lt[4] = {0.f, 0.f, 0.f, 0.f};
#pragma unroll
    for (int ks = 0; ks < 4; ks++) {
        const uint32_t a[4] = {ph[2 * ks][0], ph[2 * ks][1],
                               ph[2 * ks + 1][0], ph[2 * ks + 1][1]};
        mma16816(lt, a, ONESH2, ONESH2);
    }
    l_lo = l_lo * al + lt[0];
    l_hi = l_hi * ah + lt[2];

#pragma unroll
    for (int nd = 0; nd < 8; nd++) {
        o[nd][0] *= al; o[nd][1] *= al;
        o[nd][2] *= ah; o[nd][3] *= ah;
    }
}

__global__ void __launch_bounds__(128, 2)
fa_fwd(const float* __restrict__ Q, float* __restrict__ O) {
    extern __shared__ __half sm_[];

    const int tid  = threadIdx.x;
    const int warp = tid >> 5;
    const int lane = tid & 31;
    const int g = lane >> 2;
    const int t = lane & 3;

    const int bh    = blockIdx.y;
    const int qb    = (int)gridDim.x - 1 - (int)blockIdx.x;  // longest-first
    const int qbase = qb * BM;
    const size_t base = (size_t)bh * Tt * Dd;
    const float*  Qp = Q + base;
    const __half* Kh = g_kh + base;
    const __half* Vh = g_vh + base;
    float*        Op = O + base;

    const int wrow = warp * 32;            // warp covers rows [wrow, wrow+32)
    const int jmax = 2 * qb + 1;

    // cp.async producer indexing: 2 threads per row, 4x16B chunks each
    const int prow = tid >> 1;
    const int pcol = (tid & 1) * 32;       // halves
    const uint32_t smem_u32 = cvta_s(sm_);

    auto issue_tile = [&](int j) {
        if (j <= jmax) {
            const int st = (j & (STAGES - 1)) * STAGE_HALVES;
            const __half* ksrc = Kh + (size_t)(j * BN + prow) * Dd + pcol;
            const __half* vsrc = Vh + (size_t)(j * BN + prow) * Dd + pcol;
            uint32_t kdst = smem_u32 + (st + prow * KSTR + pcol) * 2;
            uint32_t vdst = kdst + BN * KSTR * 2;
#pragma unroll
            for (int i = 0; i < 4; i++) cpa16(kdst + i * 16, ksrc + i * 8);
#pragma unroll
            for (int i = 0; i < 4; i++) cpa16(vdst + i * 16, vsrc + i * 8);
        }
        cpa_commit();
    };

    // ---- Q A-fragments straight from gmem (pre-scaled into exp2 domain) ----
    uint32_t qa[2][4][4];
#pragma unroll
    for (int ms = 0; ms < 2; ms++) {
        const float* q0 = Qp + (size_t)(qbase + wrow + ms * 16 + g) * Dd;
        const float* q1 = q0 + 8 * Dd;
#pragma unroll
        for (int ks = 0; ks < 4; ks++) {
            int col = ks * 16 + t * 2;
            float2 x0 = *reinterpret_cast<const float2*>(q0 + col);
            float2 x1 = *reinterpret_cast<const float2*>(q1 + col);
            float2 x2 = *reinterpret_cast<const float2*>(q0 + col + 8);
            float2 x3 = *reinterpret_cast<const float2*>(q1 + col + 8);
            qa[ms][ks][0] = packh2(x0.x * QSCALE, x0.y * QSCALE);
            qa[ms][ks][1] = packh2(x1.x * QSCALE, x1.y * QSCALE);
            qa[ms][ks][2] = packh2(x2.x * QSCALE, x2.y * QSCALE);
            qa[ms][ks][3] = packh2(x3.x * QSCALE, x3.y * QSCALE);
        }
    }

    // ---- pipeline prologue: tiles 0..STAGES-2 in flight ----
#pragma unroll
    for (int j = 0; j < STAGES - 1; j++) issue_tile(j);

    float o0[8][4], o1[8][4];
#pragma unroll
    for (int nd = 0; nd < 8; nd++) {
        o0[nd][0] = 0.f; o0[nd][1] = 0.f; o0[nd][2] = 0.f; o0[nd][3] = 0.f;
        o1[nd][0] = 0.f; o1[nd][1] = 0.f; o1[nd][2] = 0.f; o1[nd][3] = 0.f;
    }
    const float NEGINF = __int_as_float(0xff800000u);
    float m0l = NEGINF, m0h = NEGINF, l0l = 0.f, l0h = 0.f;
    float m1l = NEGINF, m1h = NEGINF, l1l = 0.f, l1h = 0.f;

    for (int j = 0; j <= jmax; j++) {
        cpa_wait<STAGES - 2>();     // tile j landed (this thread's groups)
        __syncthreads();            // visible to all; stage (j-1) fully consumed
        issue_tile(j + STAGES - 1); // refill oldest stage

        const int st = (j & (STAGES - 1)) * STAGE_HALVES;
        const __half* kt = sm_ + st;
        const __half* vt = kt + BN * KSTR;
        const int kvbase = j * BN;

        const bool active = (kvbase <= qbase + wrow + 31);
        if (active) {
            // ---- S = Q K^T for both 16-row subtiles (shared K fragments) ----
            float s0[8][4], s1[8][4];
#pragma unroll
            for (int n = 0; n < 8; n++) {
                s0[n][0] = 0.f; s0[n][1] = 0.f; s0[n][2] = 0.f; s0[n][3] = 0.f;
                s1[n][0] = 0.f; s1[n][1] = 0.f; s1[n][2] = 0.f; s1[n][3] = 0.f;
            }
            const int rowa = (lane & 7);
            const int cola = 8 * (lane >> 3);
#pragma unroll
            for (int n = 0; n < 8; n++) {
                uint32_t b[8];
                uint32_t addr = cvta_s(kt + (8 * n + rowa) * KSTR + cola);
                ldsm4(b[0], b[1], b[2], b[3], addr);
                ldsm4(b[4], b[5], b[6], b[7], addr + 64);   // +32 halves
#pragma unroll
                for (int ks = 0; ks < 4; ks++) {
                    mma16816(s0[n], qa[0][ks], b[2 * ks], b[2 * ks + 1]);
                    mma16816(s1[n], qa[1][ks], b[2 * ks], b[2 * ks + 1]);
                }
            }

            // ---- causal mask (straddling tiles only) ----
            if (kvbase + BN - 1 > qbase + wrow) {
                const int q0lo = qbase + wrow + g;
                const int q0hi = q0lo + 8;
                const int q1lo = q0lo + 16;
                const int q1hi = q0lo + 24;
#pragma unroll
                for (int n = 0; n < 8; n++) {
                    int c = kvbase + n * 8 + t * 2;
                    if (c     > q0lo) s0[n][0] = NEGINF;
                    if (c + 1 > q0lo) s0[n][1] = NEGINF;
                    if (c     > q0hi) s0[n][2] = NEGINF;
                    if (c + 1 > q0hi) s0[n][3] = NEGINF;
                    if (c     > q1lo) s1[n][0] = NEGINF;
                    if (c + 1 > q1lo) s1[n][1] = NEGINF;
                    if (c     > q1hi) s1[n][2] = NEGINF;
                    if (c + 1 > q1hi) s1[n][3] = NEGINF;
                }
            }

            // ---- online softmax per subtile; P packed to fp16 A-fragments ----
            uint32_t ph0[8][2], ph1[8][2];
            softmax_sub(s0, m0l, m0h, l0l, l0h, o0, ph0);
            softmax_sub(s1, m1l, m1h, l1l, l1h, o1, ph1);

            // ---- O += P V (shared V fragments for both subtiles) ----
            const int rowv0 = 8 * ((lane >> 3) & 1) + (lane & 7);
            const int cv = (lane >> 4);
#pragma unroll
            for (int ks = 0; ks < 4; ks++) {
                const uint32_t a0[4] = {ph0[2 * ks][0], ph0[2 * ks][1],
                                        ph0[2 * ks + 1][0], ph0[2 * ks + 1][1]};
                const uint32_t a1[4] = {ph1[2 * ks][0], ph1[2 * ks][1],
                                        ph1[2 * ks + 1][0], ph1[2 * ks + 1][1]};
                const __half* vrow = vt + (16 * ks + rowv0) * KSTR;
#pragma unroll
                for (int p = 0; p < 4; p++) {
                    uint32_t r0, r1, r2, r3;
                    ldsm4t(r0, r1, r2, r3, cvta_s(vrow + 8 * (2 * p + cv)));
                    mma16816(o0[2 * p],     a0, r0, r1);
                    mma16816(o0[2 * p + 1], a0, r2, r3);
                    mma16816(o1[2 * p],     a1, r0, r1);
                    mma16816(o1[2 * p + 1], a1, r2, r3);
                }
            }
        }
    }

    // ---- finalize (l already holds the full row sum — no reduction) ----
    const float i0l = 1.f / l0l, i0h = 1.f / l0h;
    const float i1l = 1.f / l1l, i1h = 1.f / l1h;

    const int r0lo = qbase + wrow + g;
    const int r1lo = r0lo + 16;
#pragma unroll
    for (int nd = 0; nd < 8; nd++) {
        int col = nd * 8 + t * 2;
        *reinterpret_cast<float2*>(Op + (size_t)r0lo * Dd + col) =
            make_float2(o0[nd][0] * i0l, o0[nd][1] * i0l);
        *reinterpret_cast<float2*>(Op + (size_t)(r0lo + 8) * Dd + col) =
            make_float2(o0[nd][2] * i0h, o0[nd][3] * i0h);
        *reinterpret_cast<float2*>(Op + (size_t)r1lo * Dd + col) =
            make_float2(o1[nd][0] * i1l, o1[nd][1] * i1l);
        *reinterpret_cast<float2*>(Op + (size_t)(r1lo + 8) * Dd + col) =
            make_float2(o1[nd][2] * i1h, o1[nd][3] * i1h);
    }
}

}  // namespace

extern "C" void kernel_launch(void* const* d_in, const int* in_sizes, int n_in,
                              void* d_out, int out_size) {
    (void)in_sizes; (void)n_in; (void)out_size;
    const float* q = (const float*)d_in[0];
    const float* k = (const float*)d_in[1];
    const float* v = (const float*)d_in[2];
    float*       o = (float*)d_out;

    conv_kv<<<2048, 256>>>(k, v);

    cudaFuncSetAttribute(fa_fwd, cudaFuncAttributeMaxDynamicSharedMemorySize,
                         SMEM_BYTES);
    dim3 grid(Tt / BM, Bb * Hh);
    fa_fwd<<<grid, 128, SMEM_BYTES>>>(q, o);
}